// round 4
// baseline (speedup 1.0000x reference)
#include <cuda_runtime.h>
#include <cuda_fp16.h>
#include <cstdint>
#include <cstddef>

// ---------------------------------------------------------------------------
// Geometry
// ---------------------------------------------------------------------------
static constexpr int KF = 4096;
static constexpr int NF = 14336;
static constexpr int MROWS = 256;         // 8*32 batch rows
static constexpr int NTILE = 128;
static constexpr int NCTA = NF / NTILE;   // 112
static constexpr int KC = 64;             // k per stage
static constexpr int NITER = KF / KC;     // 64

// fp16 image of x, pre-swizzled as the A smem tile image:
// 64 tiles (one per 64-k chunk), each 256 rows x 128B = 32KB.
__device__ __align__(128) unsigned char g_xs[64 * 32768];

// SMEM: A 2 x 32768 | B 2 x 16384
static constexpr uint32_t SM_A = 0;
static constexpr uint32_t SM_B = 65536;
static constexpr uint32_t SM_TOTAL = 98304;

// ---------------------------------------------------------------------------
// Helpers
// ---------------------------------------------------------------------------
__device__ __forceinline__ __half2 u2h(uint32_t u) { return *reinterpret_cast<__half2*>(&u); }
__device__ __forceinline__ uint32_t h2u(__half2 h) { return *reinterpret_cast<uint32_t*>(&h); }

__device__ __forceinline__ void ldsm_x4(uint32_t (&r)[4], uint32_t addr) {
    asm volatile("ldmatrix.sync.aligned.m8n8.x4.shared.b16 {%0,%1,%2,%3}, [%4];"
                 : "=r"(r[0]), "=r"(r[1]), "=r"(r[2]), "=r"(r[3]) : "r"(addr));
}
__device__ __forceinline__ void ldsm_x4_t(uint32_t& r0, uint32_t& r1, uint32_t& r2, uint32_t& r3,
                                          uint32_t addr) {
    asm volatile("ldmatrix.sync.aligned.m8n8.x4.trans.shared.b16 {%0,%1,%2,%3}, [%4];"
                 : "=r"(r0), "=r"(r1), "=r"(r2), "=r"(r3) : "r"(addr));
}
__device__ __forceinline__ void mma16816(float (&d)[4], const uint32_t (&a)[4],
                                         uint32_t b0, uint32_t b1) {
    asm volatile("mma.sync.aligned.m16n8k16.row.col.f32.f16.f16.f32 "
                 "{%0,%1,%2,%3}, {%4,%5,%6,%7}, {%8,%9}, {%0,%1,%2,%3};"
                 : "+f"(d[0]), "+f"(d[1]), "+f"(d[2]), "+f"(d[3])
                 : "r"(a[0]), "r"(a[1]), "r"(a[2]), "r"(a[3]), "r"(b0), "r"(b1));
}

// ---------------------------------------------------------------------------
// Kernel 1: x fp32 -> fp16 into pre-swizzled A tile images.
// Tile c (k in [64c, 64c+64)); byte(m, kl) = m*128 + (((kl>>3)^(m&7))<<4) + (kl&7)*2
// ---------------------------------------------------------------------------
__global__ __launch_bounds__(256) void prep_x_kernel(const float* __restrict__ x) {
    int idx = blockIdx.x * 256 + threadIdx.x;      // one fp16 pair each; 524288 total
    int m = idx >> 11;
    int k = (idx & 2047) * 2;
    float2 v = *reinterpret_cast<const float2*>(x + (size_t)m * KF + k);
    __half2 h = __floats2half2_rn(v.x, v.y);
    int c = k >> 6, kl = k & 63;
    uint32_t off = (uint32_t)m * 128u + ((((uint32_t)(kl >> 3)) ^ (uint32_t)(m & 7)) << 4)
                 + (uint32_t)(kl & 7) * 2u;
    *reinterpret_cast<uint32_t*>(g_xs + (size_t)c * 32768 + off) = h2u(h);
}

// ---------------------------------------------------------------------------
// Kernel 2: GEMM. 112 CTAs x 256 threads. CTA: M=256, N=128, K=4096.
// 8 warps as 4(m) x 2(n); warp tile 64m x 64n; fp32 accum (128 regs).
// ---------------------------------------------------------------------------
__global__ __launch_bounds__(256, 1)
void gemm_kernel(const int* __restrict__ qk, const float* __restrict__ qs,
                 const float* __restrict__ qzb, const float* __restrict__ bias,
                 float* __restrict__ out) {
    extern __shared__ unsigned char smem[];
    const uint32_t sb = (uint32_t)__cvta_generic_to_shared(smem);
    const int t = threadIdx.x, lane = t & 31, w = t >> 5;
    const int wm = w >> 1, wn = w & 1;
    const int n0 = blockIdx.x * NTILE;

    // ---- dequant mapping: lane -> n quad, warp -> k row set ----
    const int nq = lane;                 // n = 4*nq
    const int kw = w;                    // k = kw + 8*j
    const uint32_t sts_base = (uint32_t)kw * 256u
                            + ((uint32_t)((nq >> 1) ^ kw) << 4) + (uint32_t)(nq & 1) * 8u;
    const int*   qbase = qk  + n0 + nq * 4;
    const float* sbase = qs  + n0 + nq * 4;
    const float* zbase = qzb + n0 + nq * 4;

    // ---- ldmatrix address precompute ----
    const int l15 = lane & 15;
    const uint32_t sx = (uint32_t)(lane & 7);
    const uint32_t lq = (uint32_t)(lane >> 4);
    uint32_t a_row[4];
#pragma unroll
    for (int mb = 0; mb < 4; mb++)
        a_row[mb] = (uint32_t)(wm * 64 + mb * 16 + l15) * 128u;
    const uint32_t b_row = (uint32_t)l15 * 256u + (uint32_t)wn * 128u;

    float d[4][8][4];
#pragma unroll
    for (int mb = 0; mb < 4; mb++)
#pragma unroll
        for (int nb = 0; nb < 8; nb++)
#pragma unroll
            for (int i = 0; i < 4; i++) d[mb][nb][i] = 0.0f;

    int4 bq[8];
    uint32_t s01, s23, z01, z23;

    // ---- prefetch: A cp.async + B LDGs + scales for chunk c into regs ----
    auto prefetch = [&](int c, int st) {
        const unsigned char* asrc = g_xs + (size_t)c * 32768 + (size_t)t * 16;
        uint32_t adst = sb + SM_A + (uint32_t)st * 32768u + (uint32_t)t * 16u;
#pragma unroll
        for (int i = 0; i < 8; i++) {
            asm volatile("cp.async.cg.shared.global [%0], [%1], 16;"
                         :: "r"(adst + (uint32_t)i * 4096u), "l"(asrc + (size_t)i * 4096)
                         : "memory");
        }
        asm volatile("cp.async.commit_group;" ::: "memory");

        const int* qp = qbase + (size_t)c * KC * NF;
#pragma unroll
        for (int j = 0; j < 8; j++)
            bq[j] = *reinterpret_cast<const int4*>(qp + (size_t)(kw + 8 * j) * NF);

        int g = c >> 1;   // quant group (128 k per group, 64 k per chunk)
        float4 s4 = *reinterpret_cast<const float4*>(sbase + (size_t)g * NF);
        float4 z4 = *reinterpret_cast<const float4*>(zbase + (size_t)g * NF);
        s01 = h2u(__floats2half2_rn(s4.x, s4.y)); s23 = h2u(__floats2half2_rn(s4.z, s4.w));
        z01 = h2u(__floats2half2_rn(z4.x, z4.y)); z23 = h2u(__floats2half2_rn(z4.z, z4.w));
    };

    // ---- dequant regs -> STS into B tile of stage st ----
    auto store_b = [&](int st) {
        const __half2 h1024 = u2h(0x64006400u);
        uint32_t base = sb + SM_B + (uint32_t)st * 16384u + sts_base;
#pragma unroll
        for (int j = 0; j < 8; j++) {
            uint32_t u01 = ((uint32_t)bq[j].x | ((uint32_t)bq[j].y << 16)) | 0x64006400u;
            uint32_t u23 = ((uint32_t)bq[j].z | ((uint32_t)bq[j].w << 16)) | 0x64006400u;
            __half2 q01 = __hsub2(u2h(u01), h1024);      // exact q values
            __half2 q23 = __hsub2(u2h(u23), h1024);
            uint32_t w01 = h2u(__hfma2(q01, u2h(s01), u2h(z01)));
            uint32_t w23 = h2u(__hfma2(q23, u2h(s23), u2h(z23)));
            asm volatile("st.shared.v2.b32 [%0], {%1,%2};"
                         :: "r"(base + (uint32_t)j * 2048u), "r"(w01), "r"(w23) : "memory");
        }
    };

    // ---- mma over one stage ----
    auto compute = [&](int st) {
        uint32_t abase = sb + SM_A + (uint32_t)st * 32768u;
        uint32_t bbase = sb + SM_B + (uint32_t)st * 16384u + b_row;
#pragma unroll
        for (int ks = 0; ks < 4; ks++) {
            uint32_t a[4][4];
#pragma unroll
            for (int mb = 0; mb < 4; mb++)
                ldsm_x4(a[mb], abase + a_row[mb] + ((((uint32_t)(2 * ks) + lq) ^ sx) << 4));
            uint32_t b[8][2];
#pragma unroll
            for (int p = 0; p < 4; p++)
                ldsm_x4_t(b[2 * p][0], b[2 * p][1], b[2 * p + 1][0], b[2 * p + 1][1],
                          bbase + (uint32_t)ks * 4096u + ((((uint32_t)(2 * p) + lq) ^ sx) << 4));
#pragma unroll
            for (int mb = 0; mb < 4; mb++)
#pragma unroll
                for (int nb = 0; nb < 8; nb++)
                    mma16816(d[mb][nb], a[mb], b[nb][0], b[nb][1]);
        }
    };

    // ---- prologue ----
    prefetch(0, 0);
    store_b(0);
    asm volatile("cp.async.wait_group 0;" ::: "memory");
    __syncthreads();

    // ---- main loop (double buffered) ----
    for (int c = 0; c < NITER; c++) {
        int st = c & 1;
        if (c + 1 < NITER) prefetch(c + 1, st ^ 1);
        compute(st);
        if (c + 1 < NITER) {
            store_b(st ^ 1);
            asm volatile("cp.async.wait_group 0;" ::: "memory");
        }
        __syncthreads();
    }

    // ---- epilogue: accum + bias -> out ----
    const int gr = lane >> 2;
    const int c2 = (lane & 3) * 2;
#pragma unroll
    for (int mb = 0; mb < 4; mb++) {
        int m = wm * 64 + mb * 16 + gr;
#pragma unroll
        for (int nb = 0; nb < 8; nb++) {
            int n = n0 + wn * 64 + nb * 8 + c2;
            float2 bv = *reinterpret_cast<const float2*>(bias + n);
            float2 o0, o1;
            o0.x = d[mb][nb][0] + bv.x; o0.y = d[mb][nb][1] + bv.y;
            o1.x = d[mb][nb][2] + bv.x; o1.y = d[mb][nb][3] + bv.y;
            *reinterpret_cast<float2*>(out + (size_t)m * NF + n)       = o0;
            *reinterpret_cast<float2*>(out + (size_t)(m + 8) * NF + n) = o1;
        }
    }
}

// ---------------------------------------------------------------------------
// kernel_launch
// ---------------------------------------------------------------------------
extern "C" void kernel_launch(void* const* d_in, const int* in_sizes, int n_in,
                              void* d_out, int out_size) {
    const float* x    = (const float*)d_in[0];
    const int*   qk   = (const int*)d_in[1];
    const float* qs   = (const float*)d_in[2];
    const float* qzb  = (const float*)d_in[3];
    const float* bias = (const float*)d_in[4];
    float* out = (float*)d_out;

    cudaFuncSetAttribute(gemm_kernel, cudaFuncAttributeMaxDynamicSharedMemorySize, SM_TOTAL);

    prep_x_kernel<<<(MROWS * KF / 2) / 256, 256>>>(x);
    gemm_kernel<<<NCTA, 256, SM_TOTAL>>>(qk, qs, qzb, bias, out);
}